// round 12
// baseline (speedup 1.0000x reference)
#include <cuda_runtime.h>
#include <cstdint>

#define Bb 8
#define Tt 2048
#define Cc 1024
#define HS 64
#define CH 4              // key-tiles (128 keys) per split-KV chunk
#define NSLOT 4
#define WPB 40            // sum_{rb=0}^{15} ceil((rb+1)/4)

__device__ __align__(16) float g_Q[Bb*Tt*HS];
__device__ __align__(16) float g_K[Bb*Tt*HS];      // tf32-rounded
__device__ __align__(16) float g_V[Bb*Tt*HS];      // tf32-rounded
__device__ __align__(16) float g_Op[NSLOT*Bb*Tt*HS];
__device__ __align__(16) float g_Lp[NSLOT*Bb*Tt];
__device__ __align__(16) uint32_t g_Bpk[64 * 3072]; // 64 k-chunks x 192 n-rows x 16 words

__device__ __forceinline__ uint32_t tf32r(float f) {
    uint32_t r; asm("cvt.rna.tf32.f32 %0, %1;" : "=r"(r) : "f"(f)); return r;
}
__device__ __forceinline__ float ex2f(float x) {
    float r; asm("ex2.approx.f32 %0, %1;" : "=f"(r) : "f"(x)); return r;
}
__device__ __forceinline__ void mma8(float4& d, uint32_t a0, uint32_t a1, uint32_t a2, uint32_t a3,
                                     uint32_t b0, uint32_t b1) {
    asm("mma.sync.aligned.m16n8k8.row.col.f32.tf32.tf32.f32 "
        "{%0,%1,%2,%3}, {%4,%5,%6,%7}, {%8,%9}, {%0,%1,%2,%3};"
        : "+f"(d.x), "+f"(d.y), "+f"(d.z), "+f"(d.w)
        : "r"(a0), "r"(a1), "r"(a2), "r"(a3), "r"(b0), "r"(b1));
}
__device__ __forceinline__ uint32_t smem_u32(const void* p) {
    uint32_t a;
    asm("{ .reg .u64 t; cvta.to.shared.u64 t, %1; cvt.u32.u64 %0, t; }" : "=r"(a) : "l"(p));
    return a;
}
__device__ __forceinline__ void cpa16(uint32_t dst, const void* src) {
    asm volatile("cp.async.cg.shared.global [%0], [%1], 16;" :: "r"(dst), "l"(src));
}
#define CP_COMMIT() asm volatile("cp.async.commit_group;" ::: "memory")
#define CP_WAIT0()  asm volatile("cp.async.wait_group 0;" ::: "memory")

// ============================================================================
// Prep (unchanged R11): weights -> permuted + XOR-swizzled tf32 image.
// Word layout of row n (16 words): word[((k&3)^(n&3))*4 + (k>>2)] = W[k][n].
// ============================================================================
__global__ __launch_bounds__(256) void prep_b(
    const float* __restrict__ Wq, const float* __restrict__ Wk, const float* __restrict__ Wv)
{
    const int ch = blockIdx.x;
    #pragma unroll
    for (int i = 0; i < 12; i++) {
        const int idx = threadIdx.x + i * 256;    // 0..3071
        const int n = idx >> 4, wd = idx & 15;
        const int k = ((wd & 3) << 2) | ((wd >> 2) ^ (n & 3));
        const float* W = (n < 64) ? Wq : (n < 128) ? Wk : Wv;
        g_Bpk[ch * 3072 + idx] = tf32r(W[(size_t)(ch * 16 + k) * HS + (n & 63)]);
    }
}

// ============================================================================
// Fused QKV: CTA 64x192, BK=32 (two independent 16-k blocks per stage),
// 8 warps (2m x 4n), warp tile 32x48. Swizzled 16-word rows: all fragment
// loads are conflict-free LDS.128 (same bank proofs as R11, per 16-block).
// 32 iterations, 1 sync/iter, 2 CTAs/SM, 64KB dynamic smem.
//
// smem word map: A(st,h) = st*2048 + h*1024   (64 rows x 16 words)
//                B(st,h) = 4096 + st*6144 + h*3072  (192 rows x 16 words)
// ============================================================================
#define QKV_SMEM ((4096 + 12288) * 4)   // 65536 bytes
__global__ __launch_bounds__(256, 2) void qkv_mma(const float* __restrict__ x)
{
    extern __shared__ uint32_t sm[];
    const int tid = threadIdx.x;
    const int w = tid >> 5, lane = tid & 31;
    const int g = lane >> 2, t = lane & 3;
    const int wm = w >> 2, wn = w & 3;
    const int m0 = blockIdx.x * 64;

    float4 acc[2][6];
    #pragma unroll
    for (int i = 0; i < 2; i++)
        #pragma unroll
        for (int j = 0; j < 6; j++) acc[i][j] = make_float4(0.f, 0.f, 0.f, 0.f);

    const int ar = tid >> 2, aq0 = tid & 3;
    const int asw = ar & 3;
    const bool bldr = (tid < 192);
    const uint32_t sbase = smem_u32(sm);
    const uint32_t bq0 = sbase + (4096u + (uint32_t)tid * 16) * 4;     // st=0,h=0 row
    const float* xrow = x + (size_t)(m0 + ar) * Cc;

    // prologue: B chunk-pair 0 (both halves), A chunk-pair 0 into regs
    if (bldr) {
        const uint32_t* s0 = g_Bpk + tid * 16;           // chunk 0
        const uint32_t* s1 = g_Bpk + 3072 + tid * 16;    // chunk 1
        #pragma unroll
        for (int j = 0; j < 4; j++) cpa16(bq0 + j * 16, s0 + j * 4);
        #pragma unroll
        for (int j = 0; j < 4; j++) cpa16(bq0 + 3072u * 4 + j * 16, s1 + j * 4);
    }
    CP_COMMIT();
    float4 a_s0 = *(const float4*)(xrow + aq0 * 4);
    float4 a_s1 = *(const float4*)(xrow + 16 + aq0 * 4);

    const int fsw = ((t ^ (g & 3)) << 2);
    const int raw = (wm * 32 + g) * 16;              // A row base within 16-block
    const int rbw = (wn * 48 + g) * 16;              // B row base within 16-block

    #pragma unroll 1
    for (int ch = 0; ch < 32; ch++) {
        const int st = ch & 1;
        {
            uint32_t* A0 = sm + st * 2048 + ar * 16 + aq0;
            A0[((0 ^ asw) << 2)] = tf32r(a_s0.x);
            A0[((1 ^ asw) << 2)] = tf32r(a_s0.y);
            A0[((2 ^ asw) << 2)] = tf32r(a_s0.z);
            A0[((3 ^ asw) << 2)] = tf32r(a_s0.w);
            uint32_t* A1 = A0 + 1024;
            A1[((0 ^ asw) << 2)] = tf32r(a_s1.x);
            A1[((1 ^ asw) << 2)] = tf32r(a_s1.y);
            A1[((2 ^ asw) << 2)] = tf32r(a_s1.z);
            A1[((3 ^ asw) << 2)] = tf32r(a_s1.w);
        }
        CP_WAIT0();
        __syncthreads();
        if (ch < 31) {
            if (bldr) {
                const uint32_t nst = st ^ 1;
                const uint32_t* s0 = g_Bpk + (size_t)(2 * ch + 2) * 3072 + tid * 16;
                const uint32_t dst = sbase + (4096u + nst * 6144u + (uint32_t)tid * 16) * 4;
                #pragma unroll
                for (int j = 0; j < 4; j++) cpa16(dst + j * 16, s0 + j * 4);
                #pragma unroll
                for (int j = 0; j < 4; j++) cpa16(dst + 3072u * 4 + j * 16, s0 + 3072 + j * 4);
            }
            CP_COMMIT();
            a_s0 = *(const float4*)(xrow + (ch + 1) * 32 + aq0 * 4);
            a_s1 = *(const float4*)(xrow + (ch + 1) * 32 + 16 + aq0 * 4);
        }
        #pragma unroll
        for (int h = 0; h < 2; h++) {
            const uint32_t* Ah = sm + st * 2048 + h * 1024 + raw + fsw;
            const uint4 A0a = *(const uint4*)(Ah);
            const uint4 A8a = *(const uint4*)(Ah + 128);
            const uint4 A0b = *(const uint4*)(Ah + 256);
            const uint4 A8b = *(const uint4*)(Ah + 384);
            const uint32_t* Bh = sm + 4096 + st * 6144 + h * 3072 + rbw + fsw;
            #pragma unroll
            for (int ns = 0; ns < 6; ns++) {
                const uint4 Bv = *(const uint4*)(Bh + ns * 128);
                mma8(acc[0][ns], A0a.x, A8a.x, A0a.y, A8a.y, Bv.x, Bv.y);   // kk=0
                mma8(acc[0][ns], A0a.z, A8a.z, A0a.w, A8a.w, Bv.z, Bv.w);   // kk=1
                mma8(acc[1][ns], A0b.x, A8b.x, A0b.y, A8b.y, Bv.x, Bv.y);
                mma8(acc[1][ns], A0b.z, A8b.z, A0b.w, A8b.w, Bv.z, Bv.w);
            }
        }
    }
    // epilogue (unchanged): Q raw; K,V tf32-rounded plain layout
    #pragma unroll
    for (int sub = 0; sub < 2; sub++) {
        #pragma unroll
        for (int ns = 0; ns < 6; ns++) {
            const int cb = wn * 48 + ns * 8;
            float* base = (cb < 64) ? g_Q : (cb < 128) ? g_K : g_V;
            const bool rnd = (cb >= 64);
            const int c = (cb & 63) + 2 * t;
            const size_t r = (size_t)(m0 + wm * 32 + sub * 16 + g);
            float4 v = acc[sub][ns];
            if (rnd) {
                v.x = __uint_as_float(tf32r(v.x)); v.y = __uint_as_float(tf32r(v.y));
                v.z = __uint_as_float(tf32r(v.z)); v.w = __uint_as_float(tf32r(v.w));
            }
            *(float2*)(base + r * HS + c)       = make_float2(v.x, v.y);
            *(float2*)(base + (r + 8) * HS + c) = make_float2(v.z, v.w);
        }
    }
}

// ============================================================================
// Split-KV causal attention (exact R8): fused per-8-key S -> softmax -> PV,
// 2 CTAs/SM, K/V staged raw via cp.async, scalar fragment gathers.
// ============================================================================
#define KLDK 68
#define KLDV 72
#define SMEM_ATTN ((128 * KLDK + 128 * KLDV) * 4)

__global__ __launch_bounds__(256, 2) void attn_part(void)
{
    extern __shared__ uint32_t smv[];
    uint32_t* Ks = smv;
    uint32_t* Vs = smv + 128 * KLDK;
    const uint32_t ks_b = smem_u32(Ks), vs_b = smem_u32(Vs);

    const int item = (gridDim.x - 1) - blockIdx.x;
    const int b = item / WPB;
    int r = item % WPB, rb = 0;
    #pragma unroll 1
    while (true) { int n = (rb + CH) >> 2; if (r < n) break; r -= n; rb++; }
    const int chunk = r;
    const int t0 = chunk * CH;
    const int t1 = (t0 + CH < rb + 1) ? (t0 + CH) : (rb + 1);
    const int qbase = rb * 128;

    const int tid = threadIdx.x;
    const int w = tid >> 5, lane = tid & 31;
    const int g = lane >> 2, t = lane & 3;
    const int qrow_lo = qbase + w * 16 + g;
    const int qrow_hi = qrow_lo + 8;

    const float qscale = 1.4426950408889634f / 32.0f;
    uint32_t aq[8][4];
    {
        const float* r0 = g_Q + ((size_t)b * Tt + qrow_lo) * HS;
        const float* r1 = r0 + 8 * HS;
        #pragma unroll
        for (int kk = 0; kk < 8; kk++) {
            aq[kk][0] = tf32r(r0[kk * 8 + t] * qscale);
            aq[kk][1] = tf32r(r1[kk * 8 + t] * qscale);
            aq[kk][2] = tf32r(r0[kk * 8 + t + 4] * qscale);
            aq[kk][3] = tf32r(r1[kk * 8 + t + 4] * qscale);
        }
    }

    float4 acc_o[8];
    #pragma unroll
    for (int i = 0; i < 8; i++) acc_o[i] = make_float4(0.f, 0.f, 0.f, 0.f);
    float lsum_lo = 0.f, lsum_hi = 0.f;

    const float* Kg = g_K + (size_t)b * Tt * HS;
    const float* Vg = g_V + (size_t)b * Tt * HS;
    const int srcq0 = (lane & ~3) | (t >> 1);
    const int srcq1 = srcq0 | 2;
    const bool odd = (t & 1);

    #pragma unroll 1
    for (int tt = t0; tt < t1; tt++) {
        const int j0 = tt * 128;
        __syncthreads();
        #pragma unroll
        for (int i = 0; i < 8; i++) {
            int u = tid + i * 256;
            int rr = u >> 4, c = (u & 15) * 4;
            cpa16(ks_b + (uint32_t)(rr * KLDK + c) * 4, Kg + (size_t)(j0 + rr) * HS + c);
            cpa16(vs_b + (uint32_t)(rr * KLDV + c) * 4, Vg + (size_t)(j0 + rr) * HS + c);
        }
        CP_COMMIT();
        CP_WAIT0();
        __syncthreads();

        const bool last_tile = (tt == rb);
        #pragma unroll 1
        for (int ns = 0; ns < 16; ns++) {
            float4 cs = make_float4(0.f, 0.f, 0.f, 0.f);
            #pragma unroll
            for (int kk = 0; kk < 8; kk++) {
                uint32_t b0 = Ks[(ns * 8 + g) * KLDK + kk * 8 + t];
                uint32_t b1 = Ks[(ns * 8 + g) * KLDK + kk * 8 + t + 4];
                mma8(cs, aq[kk][0], aq[kk][1], aq[kk][2], aq[kk][3], b0, b1);
            }
            float px = ex2f(cs.x), py = ex2f(cs.y), pz = ex2f(cs.z), pw = ex2f(cs.w);
            if (last_tile) {
                const int cx = j0 + ns * 8 + 2 * t, cy = cx + 1;
                if (cx > qrow_lo) px = 0.f;
                if (cy > qrow_lo) py = 0.f;
                if (cx > qrow_hi) pz = 0.f;
                if (cy > qrow_hi) pw = 0.f;
            }
            uint32_t ux = tf32r(px), uy = tf32r(py), uz = tf32r(pz), uw = tf32r(pw);
            lsum_lo += __uint_as_float(ux) + __uint_as_float(uy);
            lsum_hi += __uint_as_float(uz) + __uint_as_float(uw);
            uint32_t xA = __shfl_sync(0xffffffffu, ux, srcq0);
            uint32_t yA = __shfl_sync(0xffffffffu, uy, srcq0);
            uint32_t zA = __shfl_sync(0xffffffffu, uz, srcq0);
            uint32_t wA = __shfl_sync(0xffffffffu, uw, srcq0);
            uint32_t xB = __shfl_sync(0xffffffffu, ux, srcq1);
            uint32_t yB = __shfl_sync(0xffffffffu, uy, srcq1);
            uint32_t zB = __shfl_sync(0xffffffffu, uz, srcq1);
            uint32_t wB = __shfl_sync(0xffffffffu, uw, srcq1);
            uint32_t a0 = odd ? yA : xA;
            uint32_t a1 = odd ? wA : zA;
            uint32_t a2 = odd ? yB : xB;
            uint32_t a3 = odd ? wB : zB;
            #pragma unroll
            for (int ns2 = 0; ns2 < 8; ns2++) {
                uint32_t b0 = Vs[(ns * 8 + t) * KLDV + ns2 * 8 + g];
                uint32_t b1 = Vs[(ns * 8 + t + 4) * KLDV + ns2 * 8 + g];
                mma8(acc_o[ns2], a0, a1, a2, a3, b0, b1);
            }
        }
    }

    float llo = lsum_lo;
    llo += __shfl_xor_sync(0xffffffffu, llo, 1);
    llo += __shfl_xor_sync(0xffffffffu, llo, 2);
    float lhi = lsum_hi;
    lhi += __shfl_xor_sync(0xffffffffu, lhi, 1);
    lhi += __shfl_xor_sync(0xffffffffu, lhi, 2);

    float* baseo = g_Op + (((size_t)chunk * Bb + b) * Tt + qrow_lo) * HS;
    #pragma unroll
    for (int ns2 = 0; ns2 < 8; ns2++) {
        *(float2*)(baseo + ns2 * 8 + 2 * t)          = make_float2(acc_o[ns2].x, acc_o[ns2].y);
        *(float2*)(baseo + 8 * HS + ns2 * 8 + 2 * t) = make_float2(acc_o[ns2].z, acc_o[ns2].w);
    }
    if (t == 0) {
        g_Lp[((size_t)chunk * Bb + b) * Tt + qrow_lo] = llo;
        g_Lp[((size_t)chunk * Bb + b) * Tt + qrow_hi] = lhi;
    }
}

// ============================================================================
// Combine (R8): float4/thread, <=4 slots.
// ============================================================================
__global__ __launch_bounds__(256) void attn_combine(float* __restrict__ out)
{
    const int idx4 = blockIdx.x * 256 + threadIdx.x;
    const int row  = idx4 >> 4;
    const int d4   = (idx4 & 15) * 4;
    const int trow = row & (Tt - 1);
    const int b    = row >> 11;
    const int rb   = trow >> 7;
    const int nch  = (rb + CH) >> 2;

    float4 o = make_float4(0.f, 0.f, 0.f, 0.f);
    float l = 0.f;
    #pragma unroll
    for (int s = 0; s < NSLOT; s++) {
        if (s < nch) {
            float4 v = *(const float4*)(g_Op + (((size_t)s * Bb + b) * Tt + trow) * HS + d4);
            o.x += v.x; o.y += v.y; o.z += v.z; o.w += v.w;
            l += g_Lp[((size_t)s * Bb + b) * Tt + trow];
        }
    }
    const float rl = 1.0f / l;
    *(float4*)(out + (size_t)row * HS + d4) =
        make_float4(o.x * rl, o.y * rl, o.z * rl, o.w * rl);
}

// ============================================================================
extern "C" void kernel_launch(void* const* d_in, const int* in_sizes, int n_in,
                              void* d_out, int out_size)
{
    const float* x  = (const float*)d_in[0];
    const float* Wq = (const float*)d_in[1];
    const float* Wk = (const float*)d_in[2];
    const float* Wv = (const float*)d_in[3];
    float* out = (float*)d_out;

    prep_b<<<64, 256>>>(Wq, Wk, Wv);

    cudaFuncSetAttribute(qkv_mma, cudaFuncAttributeMaxDynamicSharedMemorySize, QKV_SMEM);
    qkv_mma<<<(Bb * Tt) / 64, 256, QKV_SMEM>>>(x);

    cudaFuncSetAttribute(attn_part, cudaFuncAttributeMaxDynamicSharedMemorySize, SMEM_ATTN);
    attn_part<<<Bb * WPB, 256, SMEM_ATTN>>>();

    attn_combine<<<(Bb * Tt * (HS / 4)) / 256, 256>>>(out);
}

// round 13
// speedup vs baseline: 1.0134x; 1.0134x over previous
#include <cuda_runtime.h>
#include <cstdint>

#define Bb 8
#define Tt 2048
#define Cc 1024
#define HS 64
#define CH 4              // key-tiles (128 keys) per split-KV chunk
#define NSLOT 4
#define WPB 40            // sum_{rb=0}^{15} ceil((rb+1)/4)

__device__ __align__(16) float g_Q[Bb*Tt*HS];
__device__ __align__(16) float g_K[Bb*Tt*HS];      // tf32-rounded
__device__ __align__(16) float g_V[Bb*Tt*HS];      // tf32-rounded
__device__ __align__(16) float g_Op[NSLOT*Bb*Tt*HS];
__device__ __align__(16) float g_Lp[NSLOT*Bb*Tt];
__device__ __align__(16) uint32_t g_Bpk[64 * 3072]; // 64 k-chunks x 192 n-rows x 16 words

__device__ __forceinline__ uint32_t tf32r(float f) {
    uint32_t r; asm("cvt.rna.tf32.f32 %0, %1;" : "=r"(r) : "f"(f)); return r;
}
__device__ __forceinline__ float ex2f(float x) {
    float r; asm("ex2.approx.f32 %0, %1;" : "=f"(r) : "f"(x)); return r;
}
__device__ __forceinline__ void mma8(float4& d, uint32_t a0, uint32_t a1, uint32_t a2, uint32_t a3,
                                     uint32_t b0, uint32_t b1) {
    asm("mma.sync.aligned.m16n8k8.row.col.f32.tf32.tf32.f32 "
        "{%0,%1,%2,%3}, {%4,%5,%6,%7}, {%8,%9}, {%0,%1,%2,%3};"
        : "+f"(d.x), "+f"(d.y), "+f"(d.z), "+f"(d.w)
        : "r"(a0), "r"(a1), "r"(a2), "r"(a3), "r"(b0), "r"(b1));
}
__device__ __forceinline__ uint32_t smem_u32(const void* p) {
    uint32_t a;
    asm("{ .reg .u64 t; cvta.to.shared.u64 t, %1; cvt.u32.u64 %0, t; }" : "=r"(a) : "l"(p));
    return a;
}
__device__ __forceinline__ void cpa16(uint32_t dst, const void* src) {
    asm volatile("cp.async.cg.shared.global [%0], [%1], 16;" :: "r"(dst), "l"(src));
}
#define CP_COMMIT() asm volatile("cp.async.commit_group;" ::: "memory")
#define CP_WAIT0()  asm volatile("cp.async.wait_group 0;" ::: "memory")
#define CP_WAIT1()  asm volatile("cp.async.wait_group 1;" ::: "memory")

// ============================================================================
// Prep (unchanged R11): weights -> permuted + XOR-swizzled tf32 image.
// Word layout of row n (16 words): word[((k&3)^(n&3))*4 + (k>>2)] = W[k][n].
// ============================================================================
__global__ __launch_bounds__(256) void prep_b(
    const float* __restrict__ Wq, const float* __restrict__ Wk, const float* __restrict__ Wv)
{
    const int ch = blockIdx.x;
    #pragma unroll
    for (int i = 0; i < 12; i++) {
        const int idx = threadIdx.x + i * 256;    // 0..3071
        const int n = idx >> 4, wd = idx & 15;
        const int k = ((wd & 3) << 2) | ((wd >> 2) ^ (n & 3));
        const float* W = (n < 64) ? Wq : (n < 128) ? Wk : Wv;
        g_Bpk[ch * 3072 + idx] = tf32r(W[(size_t)(ch * 16 + k) * HS + (n & 63)]);
    }
}

// ============================================================================
// Fused QKV: CTA 64x192, BK=16, 8 warps (2m x 4n), warp tile 32x48,
// XOR-swizzled 16-word rows (all fragment loads conflict-free LDS.128).
// 3-stage pipeline, prefetch depth 2: B via cp.async ring (wait_group 1),
// A via 2 rotating LDG register sets. 1 sync/iter, 2 CTAs/SM, 48KB smem.
//
// smem word map: A stage s at s*1024 (64 rows x 16 words)
//                B stage s at 3072 + s*3072 (192 rows x 16 words)
// ============================================================================
#define QKV_SMEM (12288 * 4)   // 49152 bytes
__global__ __launch_bounds__(256, 2) void qkv_mma(const float* __restrict__ x)
{
    extern __shared__ uint32_t sm[];
    const int tid = threadIdx.x;
    const int w = tid >> 5, lane = tid & 31;
    const int g = lane >> 2, t = lane & 3;
    const int wm = w >> 2, wn = w & 3;
    const int m0 = blockIdx.x * 64;

    float4 acc[2][6];
    #pragma unroll
    for (int i = 0; i < 2; i++)
        #pragma unroll
        for (int j = 0; j < 6; j++) acc[i][j] = make_float4(0.f, 0.f, 0.f, 0.f);

    const int ar = tid >> 2, aq0 = tid & 3;
    const int asw = ar & 3;
    const bool bldr = (tid < 192);
    const uint32_t sbase = smem_u32(sm);
    const float* xrow = x + (size_t)(m0 + ar) * Cc;
    const uint32_t* bsrc = g_Bpk + tid * 16;

    // prologue: B chunks 0,1 as two cp.async groups; A chunks 0,1 into regs
    if (bldr) {
        const uint32_t d0 = sbase + (3072u + (uint32_t)tid * 16) * 4;
        #pragma unroll
        for (int j = 0; j < 4; j++) cpa16(d0 + j * 16, bsrc + j * 4);
    }
    CP_COMMIT();
    if (bldr) {
        const uint32_t d1 = sbase + (3072u + 3072u + (uint32_t)tid * 16) * 4;
        #pragma unroll
        for (int j = 0; j < 4; j++) cpa16(d1 + j * 16, bsrc + 3072 + j * 4);
    }
    CP_COMMIT();
    float4 a_r0 = *(const float4*)(xrow + aq0 * 4);
    float4 a_r1 = *(const float4*)(xrow + 16 + aq0 * 4);

    const int fsw = ((t ^ (g & 3)) << 2);
    const int raw = (wm * 32 + g) * 16;
    const int rbw = (wn * 48 + g) * 16;

    #pragma unroll 2
    for (int ch = 0; ch < 64; ch++) {
        const int s = ch % 3;
        // stage A(ch) from the older reg set
        {
            const float4 av = (ch & 1) ? a_r1 : a_r0;
            uint32_t* A = sm + s * 1024 + ar * 16 + aq0;
            A[((0 ^ asw) << 2)] = tf32r(av.x);
            A[((1 ^ asw) << 2)] = tf32r(av.y);
            A[((2 ^ asw) << 2)] = tf32r(av.z);
            A[((3 ^ asw) << 2)] = tf32r(av.w);
        }
        if (ch >= 62) { CP_WAIT0(); } else { CP_WAIT1(); }   // B(ch) resident
        __syncthreads();
        if (ch < 62) {
            const int s2 = (ch + 2) % 3;
            if (bldr) {
                const uint32_t* src = bsrc + (size_t)(ch + 2) * 3072;
                const uint32_t dst = sbase + (3072u + (uint32_t)s2 * 3072u + (uint32_t)tid * 16) * 4;
                #pragma unroll
                for (int j = 0; j < 4; j++) cpa16(dst + j * 16, src + j * 4);
            }
            CP_COMMIT();
            const float4 anew = *(const float4*)(xrow + (ch + 2) * 16 + aq0 * 4);
            if (ch & 1) a_r1 = anew; else a_r0 = anew;
        }
        // fragments: uint4 = k in {t, t+4, t+8, t+12}
        const uint32_t* Ap = sm + s * 1024 + raw + fsw;
        const uint4 A0a = *(const uint4*)(Ap);
        const uint4 A8a = *(const uint4*)(Ap + 128);
        const uint4 A0b = *(const uint4*)(Ap + 256);
        const uint4 A8b = *(const uint4*)(Ap + 384);
        const uint32_t* Bp = sm + 3072 + s * 3072 + rbw + fsw;
        #pragma unroll
        for (int ns = 0; ns < 6; ns++) {
            const uint4 Bv = *(const uint4*)(Bp + ns * 128);
            mma8(acc[0][ns], A0a.x, A8a.x, A0a.y, A8a.y, Bv.x, Bv.y);   // kk=0
            mma8(acc[0][ns], A0a.z, A8a.z, A0a.w, A8a.w, Bv.z, Bv.w);   // kk=1
            mma8(acc[1][ns], A0b.x, A8b.x, A0b.y, A8b.y, Bv.x, Bv.y);
            mma8(acc[1][ns], A0b.z, A8b.z, A0b.w, A8b.w, Bv.z, Bv.w);
        }
    }
    // epilogue (unchanged): Q raw; K,V tf32-rounded plain layout
    #pragma unroll
    for (int sub = 0; sub < 2; sub++) {
        #pragma unroll
        for (int ns = 0; ns < 6; ns++) {
            const int cb = wn * 48 + ns * 8;
            float* base = (cb < 64) ? g_Q : (cb < 128) ? g_K : g_V;
            const bool rnd = (cb >= 64);
            const int c = (cb & 63) + 2 * t;
            const size_t r = (size_t)(m0 + wm * 32 + sub * 16 + g);
            float4 v = acc[sub][ns];
            if (rnd) {
                v.x = __uint_as_float(tf32r(v.x)); v.y = __uint_as_float(tf32r(v.y));
                v.z = __uint_as_float(tf32r(v.z)); v.w = __uint_as_float(tf32r(v.w));
            }
            *(float2*)(base + r * HS + c)       = make_float2(v.x, v.y);
            *(float2*)(base + (r + 8) * HS + c) = make_float2(v.z, v.w);
        }
    }
}

// ============================================================================
// Split-KV causal attention (exact R8): fused per-8-key S -> softmax -> PV,
// 2 CTAs/SM, K/V staged raw via cp.async, scalar fragment gathers.
// ============================================================================
#define KLDK 68
#define KLDV 72
#define SMEM_ATTN ((128 * KLDK + 128 * KLDV) * 4)

__global__ __launch_bounds__(256, 2) void attn_part(void)
{
    extern __shared__ uint32_t smv[];
    uint32_t* Ks = smv;
    uint32_t* Vs = smv + 128 * KLDK;
    const uint32_t ks_b = smem_u32(Ks), vs_b = smem_u32(Vs);

    const int item = (gridDim.x - 1) - blockIdx.x;
    const int b = item / WPB;
    int r = item % WPB, rb = 0;
    #pragma unroll 1
    while (true) { int n = (rb + CH) >> 2; if (r < n) break; r -= n; rb++; }
    const int chunk = r;
    const int t0 = chunk * CH;
    const int t1 = (t0 + CH < rb + 1) ? (t0 + CH) : (rb + 1);
    const int qbase = rb * 128;

    const int tid = threadIdx.x;
    const int w = tid >> 5, lane = tid & 31;
    const int g = lane >> 2, t = lane & 3;
    const int qrow_lo = qbase + w * 16 + g;
    const int qrow_hi = qrow_lo + 8;

    const float qscale = 1.4426950408889634f / 32.0f;
    uint32_t aq[8][4];
    {
        const float* r0 = g_Q + ((size_t)b * Tt + qrow_lo) * HS;
        const float* r1 = r0 + 8 * HS;
        #pragma unroll
        for (int kk = 0; kk < 8; kk++) {
            aq[kk][0] = tf32r(r0[kk * 8 + t] * qscale);
            aq[kk][1] = tf32r(r1[kk * 8 + t] * qscale);
            aq[kk][2] = tf32r(r0[kk * 8 + t + 4] * qscale);
            aq[kk][3] = tf32r(r1[kk * 8 + t + 4] * qscale);
        }
    }

    float4 acc_o[8];
    #pragma unroll
    for (int i = 0; i < 8; i++) acc_o[i] = make_float4(0.f, 0.f, 0.f, 0.f);
    float lsum_lo = 0.f, lsum_hi = 0.f;

    const float* Kg = g_K + (size_t)b * Tt * HS;
    const float* Vg = g_V + (size_t)b * Tt * HS;
    const int srcq0 = (lane & ~3) | (t >> 1);
    const int srcq1 = srcq0 | 2;
    const bool odd = (t & 1);

    #pragma unroll 1
    for (int tt = t0; tt < t1; tt++) {
        const int j0 = tt * 128;
        __syncthreads();
        #pragma unroll
        for (int i = 0; i < 8; i++) {
            int u = tid + i * 256;
            int rr = u >> 4, c = (u & 15) * 4;
            cpa16(ks_b + (uint32_t)(rr * KLDK + c) * 4, Kg + (size_t)(j0 + rr) * HS + c);
            cpa16(vs_b + (uint32_t)(rr * KLDV + c) * 4, Vg + (size_t)(j0 + rr) * HS + c);
        }
        CP_COMMIT();
        CP_WAIT0();
        __syncthreads();

        const bool last_tile = (tt == rb);
        #pragma unroll 1
        for (int ns = 0; ns < 16; ns++) {
            float4 cs = make_float4(0.f, 0.f, 0.f, 0.f);
            #pragma unroll
            for (int kk = 0; kk < 8; kk++) {
                uint32_t b0 = Ks[(ns * 8 + g) * KLDK + kk * 8 + t];
                uint32_t b1 = Ks[(ns * 8 + g) * KLDK + kk * 8 + t + 4];
                mma8(cs, aq[kk][0], aq[kk][1], aq[kk][2], aq[kk][3], b0, b1);
            }
            float px = ex2f(cs.x), py = ex2f(cs.y), pz = ex2f(cs.z), pw = ex2f(cs.w);
            if (last_tile) {
                const int cx = j0 + ns * 8 + 2 * t, cy = cx + 1;
                if (cx > qrow_lo) px = 0.f;
                if (cy > qrow_lo) py = 0.f;
                if (cx > qrow_hi) pz = 0.f;
                if (cy > qrow_hi) pw = 0.f;
            }
            uint32_t ux = tf32r(px), uy = tf32r(py), uz = tf32r(pz), uw = tf32r(pw);
            lsum_lo += __uint_as_float(ux) + __uint_as_float(uy);
            lsum_hi += __uint_as_float(uz) + __uint_as_float(uw);
            uint32_t xA = __shfl_sync(0xffffffffu, ux, srcq0);
            uint32_t yA = __shfl_sync(0xffffffffu, uy, srcq0);
            uint32_t zA = __shfl_sync(0xffffffffu, uz, srcq0);
            uint32_t wA = __shfl_sync(0xffffffffu, uw, srcq0);
            uint32_t xB = __shfl_sync(0xffffffffu, ux, srcq1);
            uint32_t yB = __shfl_sync(0xffffffffu, uy, srcq1);
            uint32_t zB = __shfl_sync(0xffffffffu, uz, srcq1);
            uint32_t wB = __shfl_sync(0xffffffffu, uw, srcq1);
            uint32_t a0 = odd ? yA : xA;
            uint32_t a1 = odd ? wA : zA;
            uint32_t a2 = odd ? yB : xB;
            uint32_t a3 = odd ? wB : zB;
            #pragma unroll
            for (int ns2 = 0; ns2 < 8; ns2++) {
                uint32_t b0 = Vs[(ns * 8 + t) * KLDV + ns2 * 8 + g];
                uint32_t b1 = Vs[(ns * 8 + t + 4) * KLDV + ns2 * 8 + g];
                mma8(acc_o[ns2], a0, a1, a2, a3, b0, b1);
            }
        }
    }

    float llo = lsum_lo;
    llo += __shfl_xor_sync(0xffffffffu, llo, 1);
    llo += __shfl_xor_sync(0xffffffffu, llo, 2);
    float lhi = lsum_hi;
    lhi += __shfl_xor_sync(0xffffffffu, lhi, 1);
    lhi += __shfl_xor_sync(0xffffffffu, lhi, 2);

    float* baseo = g_Op + (((size_t)chunk * Bb + b) * Tt + qrow_lo) * HS;
    #pragma unroll
    for (int ns2 = 0; ns2 < 8; ns2++) {
        *(float2*)(baseo + ns2 * 8 + 2 * t)          = make_float2(acc_o[ns2].x, acc_o[ns2].y);
        *(float2*)(baseo + 8 * HS + ns2 * 8 + 2 * t) = make_float2(acc_o[ns2].z, acc_o[ns2].w);
    }
    if (t == 0) {
        g_Lp[((size_t)chunk * Bb + b) * Tt + qrow_lo] = llo;
        g_Lp[((size_t)chunk * Bb + b) * Tt + qrow_hi] = lhi;
    }
}

// ============================================================================
// Combine (R8): float4/thread, <=4 slots.
// ============================================================================
__global__ __launch_bounds__(256) void attn_combine(float* __restrict__ out)
{
    const int idx4 = blockIdx.x * 256 + threadIdx.x;
    const int row  = idx4 >> 4;
    const int d4   = (idx4 & 15) * 4;
    const int trow = row & (Tt - 1);
    const int b    = row >> 11;
    const int rb   = trow >> 7;
    const int nch  = (rb + CH) >> 2;

    float4 o = make_float4(0.f, 0.f, 0.f, 0.f);
    float l = 0.f;
    #pragma unroll
    for (int s = 0; s < NSLOT; s++) {
        if (s < nch) {
            float4 v = *(const float4*)(g_Op + (((size_t)s * Bb + b) * Tt + trow) * HS + d4);
            o.x += v.x; o.y += v.y; o.z += v.z; o.w += v.w;
            l += g_Lp[((size_t)s * Bb + b) * Tt + trow];
        }
    }
    const float rl = 1.0f / l;
    *(float4*)(out + (size_t)row * HS + d4) =
        make_float4(o.x * rl, o.y * rl, o.z * rl, o.w * rl);
}

// ============================================================================
extern "C" void kernel_launch(void* const* d_in, const int* in_sizes, int n_in,
                              void* d_out, int out_size)
{
    const float* x  = (const float*)d_in[0];
    const float* Wq = (const float*)d_in[1];
    const float* Wk = (const float*)d_in[2];
    const float* Wv = (const float*)d_in[3];
    float* out = (float*)d_out;

    prep_b<<<64, 256>>>(Wq, Wk, Wv);

    cudaFuncSetAttribute(qkv_mma, cudaFuncAttributeMaxDynamicSharedMemorySize, QKV_SMEM);
    qkv_mma<<<(Bb * Tt) / 64, 256, QKV_SMEM>>>(x);

    cudaFuncSetAttribute(attn_part, cudaFuncAttributeMaxDynamicSharedMemorySize, SMEM_ATTN);
    attn_part<<<Bb * WPB, 256, SMEM_ATTN>>>();

    attn_combine<<<(Bb * Tt * (HS / 4)) / 256, 256>>>(out);
}